// round 16
// baseline (speedup 1.0000x reference)
#include <cuda_runtime.h>
#include <cuda_bf16.h>

// Embedding gather: out[token, :] = table[ids[token], :]
// ids: [32*8192] int32, table: [256,256] f32, out: [32*8192, 256] f32.
//
// Steady-state DRAM-write-roofline-bound: 268 MB of output drains to HBM
// every replay period (~6.4 TB/s sustained writes). Converged structure:
// block-contiguous output chunks, 4 independent gather->store chains per
// thread, lane-contiguous float4 (512 B / 4 L1 lines per warp instruction),
// warp-uniform ids broadcasts, table L1/L2-resident, 32-bit indexing,
// default store policy.
//
// R16 single-variable change: 128-thread blocks (32768 blocks, 8 KB each).
// Measured block-size gradient: 512thr -> 41.1 us, 256thr -> 39.2 us; the
// persistent-kernel regression (R14) showed many short blocks pipeline the
// store drain of retiring blocks with the loads of incoming ones. Testing
// whether the gradient continues at 128.

static constexpr int TOKENS       = 32 * 8192;           // 262144
static constexpr int EMBED        = 256;
static constexpr int VEC_PER_ROW  = EMBED / 4;           // 64 float4 per row
static constexpr int TOTAL_VEC4   = TOKENS * VEC_PER_ROW;// 16,777,216 (< 2^31)
static constexpr int ITEMS        = 4;                   // chains per thread
static constexpr int THREADS      = 128;

__global__ __launch_bounds__(THREADS)
void embed_gather_kernel(const int* __restrict__ ids,
                         const float4* __restrict__ table4,
                         float4* __restrict__ out4)
{
    // Block b owns float4 range [b*512, (b+1)*512), k steps by 128 (2 KB).
    const unsigned base = blockIdx.x * (unsigned)(ITEMS * THREADS) + threadIdx.x;

    unsigned g[ITEMS];
    int      tok[ITEMS];
    float4   v[ITEMS];

    // Batched index loads (warp-uniform -> single broadcast L1 hit each).
    #pragma unroll
    for (int k = 0; k < ITEMS; k++) {
        g[k]   = base + (unsigned)(k * THREADS);
        tok[k] = __ldg(&ids[g[k] >> 6]);
    }

    // Batched table loads (4 independent LDG.128; table resident in L1/L2).
    #pragma unroll
    for (int k = 0; k < ITEMS; k++) {
        v[k] = __ldg(&table4[(unsigned)tok[k] * (unsigned)VEC_PER_ROW + (g[k] & 63u)]);
    }

    // Default-policy stores: contiguous 2 KB per block per k-step.
    #pragma unroll
    for (int k = 0; k < ITEMS; k++) {
        out4[g[k]] = v[k];
    }
}

extern "C" void kernel_launch(void* const* d_in, const int* in_sizes, int n_in,
                              void* d_out, int out_size)
{
    const int*   ids   = (const int*)d_in[0];    // [32, 8192] int32
    const float* table = (const float*)d_in[1];  // [256, 256] f32
    float*       out   = (float*)d_out;          // [32, 8192, 256] f32

    const int blocks = TOTAL_VEC4 / (ITEMS * THREADS);   // 32768

    embed_gather_kernel<<<blocks, THREADS>>>(
        ids, (const float4*)table, (float4*)out);
}

// round 17
// speedup vs baseline: 1.0322x; 1.0322x over previous
#include <cuda_runtime.h>
#include <cuda_bf16.h>

// Embedding gather: out[token, :] = table[ids[token], :]
// ids: [32*8192] int32, table: [256,256] f32, out: [32*8192, 256] f32.
//
// FINAL — converged at the steady-state HBM write-drain roofline.
// 268 MB of output per replay period at ~39.2-39.8 us kernel time
// = ~6.4 TB/s sustained DRAM writes (~80% of 8 TB/s spec). Ten variants
// tested and closed:
//   - MLP depth 4 vs 8 (+reg budget so it survives into SASS): neutral
//   - scattered vs block-contiguous write order: neutral (no row lever)
//   - .cs evict-first vs default stores: default marginally better
//   - TMA bulk store (l1tex bypass): slower (STS staging also costs l1tex)
//   - id-sorted store-only streaming (counting sort): K4 alone slower
//   - persistent single-wave grid: much slower (one-shot blocks pipeline
//     retiring-block store drain with incoming-block loads across
//     boundaries; many short blocks ARE the pipeline)
//   - block size 128/256/512: 256 optimal (39.97 / 39.2 / 41.1 us)
//   - 64-bit -> 32-bit indexing: ALU 19%->6%, kept
//
// Structure: 16384 blocks x 256 threads; each block owns one contiguous
// 16 KB output chunk; each thread runs 4 independent gather->store chains
// (k steps 4 KB) with lane-contiguous float4 accesses (512 B / 4 L1 lines
// per warp instruction). ids loads are warp-uniform broadcasts; the 256 KB
// table is L1/L2-resident. Default store policy.

static constexpr int TOKENS       = 32 * 8192;           // 262144
static constexpr int EMBED        = 256;
static constexpr int VEC_PER_ROW  = EMBED / 4;           // 64 float4 per row
static constexpr int TOTAL_VEC4   = TOKENS * VEC_PER_ROW;// 16,777,216 (< 2^31)
static constexpr int ITEMS        = 4;                   // chains per thread
static constexpr int THREADS      = 256;

__global__ __launch_bounds__(THREADS)
void embed_gather_kernel(const int* __restrict__ ids,
                         const float4* __restrict__ table4,
                         float4* __restrict__ out4)
{
    // Block b owns float4 range [b*1024, (b+1)*1024), k steps by 256 (4 KB).
    const unsigned base = blockIdx.x * (unsigned)(ITEMS * THREADS) + threadIdx.x;

    unsigned g[ITEMS];
    int      tok[ITEMS];
    float4   v[ITEMS];

    // Batched index loads (warp-uniform -> single broadcast L1 hit each).
    #pragma unroll
    for (int k = 0; k < ITEMS; k++) {
        g[k]   = base + (unsigned)(k * THREADS);
        tok[k] = __ldg(&ids[g[k] >> 6]);
    }

    // Batched table loads (4 independent LDG.128; table resident in L1/L2).
    #pragma unroll
    for (int k = 0; k < ITEMS; k++) {
        v[k] = __ldg(&table4[(unsigned)tok[k] * (unsigned)VEC_PER_ROW + (g[k] & 63u)]);
    }

    // Default-policy stores: contiguous 4 KB per block per k-step.
    #pragma unroll
    for (int k = 0; k < ITEMS; k++) {
        out4[g[k]] = v[k];
    }
}

extern "C" void kernel_launch(void* const* d_in, const int* in_sizes, int n_in,
                              void* d_out, int out_size)
{
    const int*   ids   = (const int*)d_in[0];    // [32, 8192] int32
    const float* table = (const float*)d_in[1];  // [256, 256] f32
    float*       out   = (float*)d_out;          // [32, 8192, 256] f32

    const int blocks = TOTAL_VEC4 / (ITEMS * THREADS);   // 16384

    embed_gather_kernel<<<blocks, THREADS>>>(
        ids, (const float4*)table, (float4*)out);
}